// round 9
// baseline (speedup 1.0000x reference)
#include <cuda_runtime.h>

// ComplexityAnalyzer: per-image 64-bin histogram + L1 normalize + 64->32->128 MLP.
// Inputs: grad_map [B*512*512] f32, W1 [32*64], b1 [32], W2 [128*32], b2 [128].
// Output: [B*128] f32.
//
// R9 (= R8 resubmit, infra failure last round; flush cleaned): conflict-free
// transposed byte counters, FOUR disjoint arrays (one per float4 component) so
// every per-element LDS+IADD+STS chain is independent. 512 threads x 128 regs
// -> deep software pipelining; depth-4 LDG prefetch. 128 elems/thread/array ->
// bytes never overflow -> single read-once dp4a flush at the end.

#define THREADS 512
#define ITERS   128                 // 65536 float4 / 512 threads
#define AWORDS  (16 * THREADS)      // words per array (16 rows x 512 cols)
#define CNT_WORDS (4 * AWORDS)      // 4 arrays = 128 KB

__global__ __launch_bounds__(THREADS, 1)
void ca_hist_mlp_kernel(const float* __restrict__ grad,
                        const float* __restrict__ W1, const float* __restrict__ b1,
                        const float* __restrict__ W2, const float* __restrict__ b2,
                        float* __restrict__ out)
{
    extern __shared__ unsigned int cnt[];     // [4][16][512] transposed
    __shared__ float fh[64];
    __shared__ float hmid[32];
    __shared__ float inv_s;

    const int tid = threadIdx.x;
    const int img = blockIdx.x;

    // Zero 128 KB of counters (vector stores)
    {
        uint4 z = {0u, 0u, 0u, 0u};
        uint4* p = (uint4*)cnt;
        #pragma unroll
        for (int i = tid; i < CNT_WORDS / 4; i += THREADS)
            p[i] = z;
    }
    __syncthreads();

    const float4* src = (const float4*)(grad + (size_t)img * 262144u) + tid;
    unsigned int* cA = cnt + tid;
    unsigned int* cB = cA + AWORDS;
    unsigned int* cC = cB + AWORDS;
    unsigned int* cD = cC + AWORDS;

    const float scale = 64.0f / 255.0f;
    const float magic = 8388608.0f;  // 2^23

    // bin = low mantissa of fma.rz(v, 64/255, 2^23), always in [0,63].
    // word offset within array = (bin>>2)*512 = (m & 0x3C) << 7.
    #define PROC(v)                                                                  \
        do {                                                                         \
            float q0, q1, q2, q3;                                                    \
            asm("fma.rz.f32 %0, %1, %2, %3;" : "=f"(q0) : "f"((v).x), "f"(scale), "f"(magic)); \
            asm("fma.rz.f32 %0, %1, %2, %3;" : "=f"(q1) : "f"((v).y), "f"(scale), "f"(magic)); \
            asm("fma.rz.f32 %0, %1, %2, %3;" : "=f"(q2) : "f"((v).z), "f"(scale), "f"(magic)); \
            asm("fma.rz.f32 %0, %1, %2, %3;" : "=f"(q3) : "f"((v).w), "f"(scale), "f"(magic)); \
            unsigned m0 = __float_as_uint(q0), m1 = __float_as_uint(q1);             \
            unsigned m2 = __float_as_uint(q2), m3 = __float_as_uint(q3);             \
            cA[(m0 & 0x3Cu) << 7] += 1u << ((m0 & 3u) << 3);                         \
            cB[(m1 & 0x3Cu) << 7] += 1u << ((m1 & 3u) << 3);                         \
            cC[(m2 & 0x3Cu) << 7] += 1u << ((m2 & 3u) << 3);                         \
            cD[(m3 & 0x3Cu) << 7] += 1u << ((m3 & 3u) << 3);                         \
        } while (0)

    // Depth-4 register prefetch, unroll 4
    float4 p0 = __ldg(&src[0 * THREADS]);
    float4 p1 = __ldg(&src[1 * THREADS]);
    float4 p2 = __ldg(&src[2 * THREADS]);
    float4 p3 = __ldg(&src[3 * THREADS]);
    #pragma unroll 4
    for (int it = 0; it < ITERS - 4; it += 4) {
        float4 n0 = __ldg(&src[(it + 4) * THREADS]);
        float4 n1 = __ldg(&src[(it + 5) * THREADS]);
        float4 n2 = __ldg(&src[(it + 6) * THREADS]);
        float4 n3 = __ldg(&src[(it + 7) * THREADS]);
        PROC(p0); PROC(p1); PROC(p2); PROC(p3);
        p0 = n0; p1 = n1; p2 = n2; p3 = n3;
    }
    PROC(p0); PROC(p1); PROC(p2); PROC(p3);
    __syncthreads();

    // Read-once flush: warp w handles word-row w of ALL 4 arrays (row w holds
    // bins 4w..4w+3, one per byte lane). Lane l reads words [4l..4l+3] via
    // LDS.128 (lane-contiguous -> conflict-free), dp4a per byte lane.
    {
        const int w = tid >> 5;       // 16 warps <-> 16 word-rows
        const int l = tid & 31;
        int a0 = 0, a1 = 0, a2 = 0, a3 = 0;
        #pragma unroll
        for (int arr = 0; arr < 4; ++arr) {
            const uint4* row = (const uint4*)(cnt + arr * AWORDS + w * THREADS) + l;
            #pragma unroll
            for (int j = 0; j < 4; ++j) {           // 32 lanes x 4 iters x 4 words = 512
                uint4 q = row[j * 32];
                int w0 = (int)q.x, w1 = (int)q.y, w2 = (int)q.z, w3 = (int)q.w;
                a0 = __dp4a(w0, 0x00000001, a0); a0 = __dp4a(w1, 0x00000001, a0);
                a0 = __dp4a(w2, 0x00000001, a0); a0 = __dp4a(w3, 0x00000001, a0);
                a1 = __dp4a(w0, 0x00000100, a1); a1 = __dp4a(w1, 0x00000100, a1);
                a1 = __dp4a(w2, 0x00000100, a1); a1 = __dp4a(w3, 0x00000100, a1);
                a2 = __dp4a(w0, 0x00010000, a2); a2 = __dp4a(w1, 0x00010000, a2);
                a2 = __dp4a(w2, 0x00010000, a2); a2 = __dp4a(w3, 0x00010000, a2);
                a3 = __dp4a(w0, 0x01000000, a3); a3 = __dp4a(w1, 0x01000000, a3);
                a3 = __dp4a(w2, 0x01000000, a3); a3 = __dp4a(w3, 0x01000000, a3);
            }
        }
        #pragma unroll
        for (int off = 16; off > 0; off >>= 1) {
            a0 += __shfl_down_sync(0xFFFFFFFFu, a0, off);
            a1 += __shfl_down_sync(0xFFFFFFFFu, a1, off);
            a2 += __shfl_down_sync(0xFFFFFFFFu, a2, off);
            a3 += __shfl_down_sync(0xFFFFFFFFu, a3, off);
        }
        if (l == 0) {
            fh[w * 4 + 0] = (float)a0;
            fh[w * 4 + 1] = (float)a1;
            fh[w * 4 + 2] = (float)a2;
            fh[w * 4 + 3] = (float)a3;
        }
    }
    __syncthreads();

    // L1 norm denominator
    if (tid < 32) {
        float s = fh[tid] + fh[tid + 32];
        #pragma unroll
        for (int off = 16; off > 0; off >>= 1)
            s += __shfl_down_sync(0xFFFFFFFFu, s, off);
        if (tid == 0) inv_s = 1.0f / fmaxf(s, 1e-12f);
    }
    __syncthreads();
    if (tid < 64) fh[tid] *= inv_s;
    __syncthreads();

    // Layer 1: 64 -> 32 with ReLU
    if (tid < 32) {
        float acc = b1[tid];
        const float* w = W1 + tid * 64;
        #pragma unroll
        for (int b = 0; b < 64; ++b) acc = fmaf(fh[b], w[b], acc);
        hmid[tid] = fmaxf(acc, 0.0f);
    }
    __syncthreads();

    // Layer 2: 32 -> 128
    if (tid < 128) {
        float acc = b2[tid];
        const float* w = W2 + tid * 32;
        #pragma unroll
        for (int j = 0; j < 32; ++j) acc = fmaf(hmid[j], w[j], acc);
        out[img * 128 + tid] = acc;
    }
}

extern "C" void kernel_launch(void* const* d_in, const int* in_sizes, int n_in,
                              void* d_out, int out_size) {
    const float* grad = (const float*)d_in[0];
    const float* W1   = (const float*)d_in[1];
    const float* b1   = (const float*)d_in[2];
    const float* W2   = (const float*)d_in[3];
    const float* b2   = (const float*)d_in[4];
    float* out = (float*)d_out;

    static int smem_set = 0;   // idempotent attribute (not a work guard)
    if (!smem_set) {
        cudaFuncSetAttribute(ca_hist_mlp_kernel,
                             cudaFuncAttributeMaxDynamicSharedMemorySize,
                             CNT_WORDS * 4);
        smem_set = 1;
    }

    int B = in_sizes[0] / (512 * 512);
    ca_hist_mlp_kernel<<<B, THREADS, CNT_WORDS * 4>>>(grad, W1, b1, W2, b2, out);
}